// round 12
// baseline (speedup 1.0000x reference)
#include <cuda_runtime.h>
#include <cstdint>
#include <cstddef>

// Problem constants
#define Bb 64
#define Nt 577
#define Cc 768
#define Hh 12
#define SCv 0.125f
#define SPLITS 9
#define CHUNK 66        // 9*66 = 594 >= 577, divisible by G -> branchless groups
#define G 6             // tokens per group in k_attn
#define NG (CHUNK / G)  // 11 full groups per CTA

// ---------------- scratch (device globals; no allocation) ----------------
__device__ __align__(16) float g_qpart[12][Bb][Cc];            // q partial sums (kc,b,j)
__device__ __align__(16) float g_q[Bb][Cc];                    // q combined (+bias)
__device__ __align__(16) float g_t[Bb][Hh][Cc];                // SCALE * (q . Wk)
__device__ float            g_ob[Bb][Hh];                      // SCALE * (q . bk)
__device__ __align__(16) float g_pu[SPLITS][Bb][Hh][Cc];       // partial sum_n w*x
__device__ float            g_pd[SPLITS][Bb][Hh];              // partial sum_n w
__device__ __align__(16) float g_ubar[Bb][Hh][Cc];             // normalized u
__device__ __align__(16) float g_cls[Bb][Cc];                  // cls row (+bv)

// ---------------- helpers ----------------
typedef unsigned long long ull;
__device__ __forceinline__ void fma2(ull &d, ull a, ull b) {
    asm("fma.rn.f32x2 %0, %1, %2, %0;" : "+l"(d) : "l"(a), "l"(b));
}
__device__ __forceinline__ float hadd2(ull a) {
    unsigned int lo, hi;
    asm("mov.b64 {%0,%1}, %2;" : "=r"(lo), "=r"(hi) : "l"(a));
    return __uint_as_float(lo) + __uint_as_float(hi);
}
__device__ __forceinline__ void cpa16(void* dst_smem, const void* src) {
    unsigned int d = (unsigned int)__cvta_generic_to_shared(dst_smem);
    asm volatile("cp.async.cg.shared.global [%0], [%1], 16;" :: "r"(d), "l"(src));
}

// ---------------- A1: q partials (k-split GEMM), 512 threads ----------------
__global__ void __launch_bounds__(512) k_qpart(const float* __restrict__ x,
                                               const float* __restrict__ qkv_w) {
    int jc = blockIdx.x, kc = blockIdx.y;
    __shared__ float xs[64][65];
    __shared__ float ws[64][65];
    int tid = threadIdx.x;
#pragma unroll
    for (int rr = 0; rr < 2; rr++) {
        int i = tid + rr * 512;
        int r = i >> 4, c4 = (i & 15) * 4;
        float4 xv = *(const float4*)&x[(size_t)r * Nt * Cc + kc * 64 + c4];
        xs[r][c4] = xv.x; xs[r][c4 + 1] = xv.y; xs[r][c4 + 2] = xv.z; xs[r][c4 + 3] = xv.w;
        float4 wv = *(const float4*)&qkv_w[(size_t)(jc * 64 + r) * Cc + kc * 64 + c4];
        ws[r][c4] = wv.x; ws[r][c4 + 1] = wv.y; ws[r][c4 + 2] = wv.z; ws[r][c4 + 3] = wv.w;
    }
    __syncthreads();
    int ty = tid >> 4, tx = tid & 15;     // 32 x 16
    float acc[2][4] = {};
#pragma unroll 8
    for (int d = 0; d < 64; d++) {
        float a0 = xs[ty * 2 + 0][d], a1 = xs[ty * 2 + 1][d];
        float b0 = ws[tx * 4 + 0][d], b1 = ws[tx * 4 + 1][d];
        float b2 = ws[tx * 4 + 2][d], b3 = ws[tx * 4 + 3][d];
        acc[0][0] += a0 * b0; acc[0][1] += a0 * b1; acc[0][2] += a0 * b2; acc[0][3] += a0 * b3;
        acc[1][0] += a1 * b0; acc[1][1] += a1 * b1; acc[1][2] += a1 * b2; acc[1][3] += a1 * b3;
    }
#pragma unroll
    for (int i = 0; i < 2; i++) {
        float4 v = make_float4(acc[i][0], acc[i][1], acc[i][2], acc[i][3]);
        *(float4*)&g_qpart[kc][ty * 2 + i][jc * 64 + tx * 4] = v;
    }
}

// ---------------- A1b: wide combine of q partials + bias ----------------
__global__ void k_qsum(const float* __restrict__ qkv_b) {
    int idx = blockIdx.x * 256 + threadIdx.x;       // over Bb*Cc/4 = 12288
    if (idx >= Bb * Cc / 4) return;
    int b = idx / 192, j4 = (idx % 192) * 4;
    float4 s = *(const float4*)&qkv_b[j4];
#pragma unroll
    for (int kc = 0; kc < 12; kc++) {
        float4 p = *(const float4*)&g_qpart[kc][b][j4];
        s.x += p.x; s.y += p.y; s.z += p.z; s.w += p.w;
    }
    *(float4*)&g_q[b][j4] = s;
}

// ---------------- A2: t = SCALE*(q.Wk); ob, 512 thr (reads small g_q) ----------------
__global__ void __launch_bounds__(512) k_t(const float* __restrict__ qkv_w,
                                           const float* __restrict__ qkv_b) {
    int h = blockIdx.x, cc2 = blockIdx.y;
    __shared__ float qs[64][65];
    __shared__ float wk[64][65];
    int tid = threadIdx.x;
#pragma unroll
    for (int rr = 0; rr < 2; rr++) {
        int i = tid + rr * 512;
        int r = i >> 4, c4 = (i & 15) * 4;
        float4 qv = *(const float4*)&g_q[r][h * 64 + c4];
        qs[r][c4] = qv.x; qs[r][c4 + 1] = qv.y; qs[r][c4 + 2] = qv.z; qs[r][c4 + 3] = qv.w;
        float4 wv = *(const float4*)&qkv_w[(size_t)(Cc + h * 64 + r) * Cc + cc2 * 64 + c4];
        wk[r][c4] = wv.x; wk[r][c4 + 1] = wv.y; wk[r][c4 + 2] = wv.z; wk[r][c4 + 3] = wv.w;
    }
    __syncthreads();
    int ty = tid >> 4, tx = tid & 15;
    float acc[2][4] = {};
#pragma unroll 8
    for (int d = 0; d < 64; d++) {
        float a0 = qs[ty * 2 + 0][d], a1 = qs[ty * 2 + 1][d];
        float b0 = wk[d][tx * 4 + 0], b1 = wk[d][tx * 4 + 1];
        float b2 = wk[d][tx * 4 + 2], b3 = wk[d][tx * 4 + 3];
        acc[0][0] += a0 * b0; acc[0][1] += a0 * b1; acc[0][2] += a0 * b2; acc[0][3] += a0 * b3;
        acc[1][0] += a1 * b0; acc[1][1] += a1 * b1; acc[1][2] += a1 * b2; acc[1][3] += a1 * b3;
    }
#pragma unroll
    for (int i = 0; i < 2; i++) {
        float4 v = make_float4(SCv * acc[i][0], SCv * acc[i][1], SCv * acc[i][2], SCv * acc[i][3]);
        *(float4*)&g_t[ty * 2 + i][h][cc2 * 64 + tx * 4] = v;
    }
    if (cc2 == 0 && tid < 64) {
        float ssum = 0.f;
#pragma unroll 8
        for (int d = 0; d < 64; d++) ssum += qs[tid][d] * qkv_b[Cc + h * 64 + d];
        g_ob[tid][h] = SCv * ssum;
    }
}

// ---------------- B: main fused streaming kernel (R11, untouched) ----------------
__global__ void __launch_bounds__(384, 2) k_attn(const float* __restrict__ x,
                                                 float* __restrict__ out) {
    int b = blockIdx.x, sp = blockIdx.y;
    int n0 = sp * CHUNK;
    int tid = threadIdx.x;
    int w = tid >> 5, l = tid & 31;
    int g3 = l >> 3;
    int q = l & 7;

    __shared__ __align__(16) float xb[2][G][Cc];
    __shared__ __align__(16) float pl[G][12][12];
    __shared__ __align__(16) float wsm[G][16];
    __shared__ float obs[12];
    __shared__ float dsm[G * 12];

    int c1 = w * 64 + q * 8;
    ull t1[3][4];
#pragma unroll
    for (int i = 0; i < 3; i++) {
        ulonglong2 p0 = *(const ulonglong2*)&g_t[b][g3 * 3 + i][c1];
        ulonglong2 p1 = *(const ulonglong2*)&g_t[b][g3 * 3 + i][c1 + 4];
        t1[i][0] = p0.x; t1[i][1] = p0.y; t1[i][2] = p1.x; t1[i][3] = p1.y;
    }
    if (tid < 12) obs[tid] = g_ob[b][tid];

    int c2 = w * 64 + l * 2;
    float2 ua[12];
#pragma unroll
    for (int h = 0; h < 12; h++) ua[h] = make_float2(0.f, 0.f);
    float dp = 0.f;

    const float* xrow = x + (size_t)b * Nt * Cc;
    __syncthreads();

#pragma unroll
    for (int r = 0; r < 3; r++) {
        int i = tid + r * 384;
        int j = i / 192, off = (i % 192) * 4;
        int n = n0 + j; int nsrc = n < Nt ? n : Nt - 1;
        cpa16(&xb[0][j][off], xrow + (size_t)nsrc * Cc + off);
    }
    asm volatile("cp.async.commit_group;");

    for (int gi = 0; gi < NG; gi++) {
        int buf = gi & 1;
        int nbase = n0 + gi * G;
        if (gi + 1 < NG) {
            int nb2 = nbase + G;
#pragma unroll
            for (int r = 0; r < 3; r++) {
                int i = tid + r * 384;
                int j = i / 192, off = (i % 192) * 4;
                int n = nb2 + j; int nsrc = n < Nt ? n : Nt - 1;
                cpa16(&xb[buf ^ 1][j][off], xrow + (size_t)nsrc * Cc + off);
            }
        }
        asm volatile("cp.async.commit_group;");
        asm volatile("cp.async.wait_group 1;");
        __syncthreads();

        // ---- phase 1: logits ----
#pragma unroll
        for (int j = 0; j < G; j++) {
            ulonglong2 xp0 = *(const ulonglong2*)&xb[buf][j][c1];
            ulonglong2 xp1 = *(const ulonglong2*)&xb[buf][j][c1 + 4];
            ull xv0 = xp0.x, xv1 = xp0.y, xv2 = xp1.x, xv3 = xp1.y;
            float s[3];
#pragma unroll
            for (int i = 0; i < 3; i++) {
                ull a = 0ull;
                fma2(a, xv0, t1[i][0]); fma2(a, xv1, t1[i][1]);
                fma2(a, xv2, t1[i][2]); fma2(a, xv3, t1[i][3]);
                float sv = hadd2(a);
                sv += __shfl_xor_sync(0xffffffffu, sv, 4, 8);
                sv += __shfl_xor_sync(0xffffffffu, sv, 2, 8);
                sv += __shfl_xor_sync(0xffffffffu, sv, 1, 8);
                s[i] = sv;
            }
            if (q < 3) pl[j][w][g3 * 3 + q] = s[q];
        }
        __syncthreads();

        // ---- combine ----
        if (tid < G * 12) {
            int gg = tid / 12, h = tid % 12;
            int n = nbase + gg;
            float s = 0.f;
#pragma unroll
            for (int ww = 0; ww < 12; ww++) s += pl[gg][ww][h];
            float wv = (n < Nt) ? __expf(s + obs[h]) : 0.f;
            dp += wv;
            wsm[gg][h] = wv;
        }
        __syncthreads();

        // ---- phase 2 ----
#pragma unroll
        for (int j = 0; j < G; j++) {
            int n = nbase + j;
            float4 wA = *(const float4*)&wsm[j][0];
            float4 wB = *(const float4*)&wsm[j][4];
            float4 wC = *(const float4*)&wsm[j][8];
            float2 xv = *(const float2*)&xb[buf][j][c2];
            ua[0].x = fmaf(wA.x, xv.x, ua[0].x);  ua[0].y = fmaf(wA.x, xv.y, ua[0].y);
            ua[1].x = fmaf(wA.y, xv.x, ua[1].x);  ua[1].y = fmaf(wA.y, xv.y, ua[1].y);
            ua[2].x = fmaf(wA.z, xv.x, ua[2].x);  ua[2].y = fmaf(wA.z, xv.y, ua[2].y);
            ua[3].x = fmaf(wA.w, xv.x, ua[3].x);  ua[3].y = fmaf(wA.w, xv.y, ua[3].y);
            ua[4].x = fmaf(wB.x, xv.x, ua[4].x);  ua[4].y = fmaf(wB.x, xv.y, ua[4].y);
            ua[5].x = fmaf(wB.y, xv.x, ua[5].x);  ua[5].y = fmaf(wB.y, xv.y, ua[5].y);
            ua[6].x = fmaf(wB.z, xv.x, ua[6].x);  ua[6].y = fmaf(wB.z, xv.y, ua[6].y);
            ua[7].x = fmaf(wB.w, xv.x, ua[7].x);  ua[7].y = fmaf(wB.w, xv.y, ua[7].y);
            ua[8].x = fmaf(wC.x, xv.x, ua[8].x);  ua[8].y = fmaf(wC.x, xv.y, ua[8].y);
            ua[9].x = fmaf(wC.y, xv.x, ua[9].x);  ua[9].y = fmaf(wC.y, xv.y, ua[9].y);
            ua[10].x = fmaf(wC.z, xv.x, ua[10].x); ua[10].y = fmaf(wC.z, xv.y, ua[10].y);
            ua[11].x = fmaf(wC.w, xv.x, ua[11].x); ua[11].y = fmaf(wC.w, xv.y, ua[11].y);
            if (n > 0 && n < Nt)
                *(float2*)&out[((size_t)b * Nt + n) * Cc + c2] = xv;
        }
        __syncthreads();
    }

#pragma unroll
    for (int h = 0; h < 12; h++)
        *(float2*)&g_pu[sp][b][h][c2] = ua[h];
    if (tid < G * 12) dsm[tid] = dp;
    __syncthreads();
    if (tid < 12) {
        float s = 0.f;
#pragma unroll
        for (int gg = 0; gg < G; gg++) s += dsm[gg * 12 + tid];
        g_pd[sp][b][tid] = s;
    }
}

// ---------------- B2: wide combine of u partials -> normalized ubar ----------------
__global__ void k_ured(void) {
    int idx = blockIdx.x * 256 + threadIdx.x;
    if (idx >= Bb * Hh * Cc / 4) return;
    int c4 = (idx % 192) * 4;
    int h = (idx / 192) % Hh;
    int b = idx / (192 * Hh);
    float d = 0.f;
#pragma unroll
    for (int s = 0; s < SPLITS; s++) d += g_pd[s][b][h];
    float4 acc = make_float4(0.f, 0.f, 0.f, 0.f);
#pragma unroll
    for (int s = 0; s < SPLITS; s++) {
        float4 p = *(const float4*)&g_pu[s][b][h][c4];
        acc.x += p.x; acc.y += p.y; acc.z += p.z; acc.w += p.w;
    }
    float inv = 1.f / d;
    acc.x *= inv; acc.y *= inv; acc.z *= inv; acc.w *= inv;
    *(float4*)&g_ubar[b][h][c4] = acc;
}

// ---------------- C1: cls (full 768-k inside block; +bv) ----------------
// grid (12 h, 2 bhalf), 512 thr.  output tile: 32 batches x 64 d.
__global__ void __launch_bounds__(512) k_cls2(const float* __restrict__ qkv_w,
                                              const float* __restrict__ qkv_b) {
    int h = blockIdx.x, bh = blockIdx.y;
    int r0 = bh * 32;
    __shared__ float us[32][65];
    __shared__ float wv[64][65];
    int tid = threadIdx.x;
    int ty = tid >> 4, tx = tid & 15;     // 32 x 16
    float acc[4] = {};

    for (int kc = 0; kc < 12; kc++) {
        __syncthreads();
        {   // us: 32x64 = 512 float4, one per thread
            int r = tid >> 4, c4 = (tid & 15) * 4;
            float4 uv = *(const float4*)&g_ubar[r0 + r][h][kc * 64 + c4];
            us[r][c4] = uv.x; us[r][c4 + 1] = uv.y; us[r][c4 + 2] = uv.z; us[r][c4 + 3] = uv.w;
        }
#pragma unroll
        for (int rr = 0; rr < 2; rr++) {   // wv: 64x64 = 1024 float4, two per thread
            int i = tid + rr * 512;
            int d = i >> 4, c4 = (i & 15) * 4;
            float4 w4 = *(const float4*)&qkv_w[(size_t)(2 * Cc + h * 64 + d) * Cc + kc * 64 + c4];
            wv[d][c4] = w4.x; wv[d][c4 + 1] = w4.y; wv[d][c4 + 2] = w4.z; wv[d][c4 + 3] = w4.w;
        }
        __syncthreads();
#pragma unroll 8
        for (int c = 0; c < 64; c++) {
            float a = us[ty][c];
            acc[0] = fmaf(a, wv[tx * 4 + 0][c], acc[0]);
            acc[1] = fmaf(a, wv[tx * 4 + 1][c], acc[1]);
            acc[2] = fmaf(a, wv[tx * 4 + 2][c], acc[2]);
            acc[3] = fmaf(a, wv[tx * 4 + 3][c], acc[3]);
        }
    }
    float4 bv = *(const float4*)&qkv_b[2 * Cc + h * 64 + tx * 4];
    float4 v = make_float4(acc[0] + bv.x, acc[1] + bv.y, acc[2] + bv.z, acc[3] + bv.w);
    *(float4*)&g_cls[r0 + ty][h * 64 + tx * 4] = v;
}

// ---------------- C2: proj (full 768-k inside block) -> out[:,0,:] directly ----------------
// grid (12 jc, 4 bq), 512 thr.  output tile: 16 batches x 64 j.
__global__ void __launch_bounds__(512) k_proj2(const float* __restrict__ proj_w,
                                               const float* __restrict__ proj_b,
                                               float* __restrict__ out) {
    int jc = blockIdx.x, bq = blockIdx.y;
    int r0 = bq * 16;
    __shared__ float cs[16][65];
    __shared__ float pw[64][65];
    int tid = threadIdx.x;
    int ty = tid >> 5, tx = tid & 31;     // 16 x 32
    float acc[2] = {};

    for (int kc = 0; kc < 12; kc++) {
        __syncthreads();
        if (tid < 256) {   // cs: 16x64 = 256 float4
            int r = tid >> 4, c4 = (tid & 15) * 4;
            float4 cv = *(const float4*)&g_cls[r0 + r][kc * 64 + c4];
            cs[r][c4] = cv.x; cs[r][c4 + 1] = cv.y; cs[r][c4 + 2] = cv.z; cs[r][c4 + 3] = cv.w;
        }
#pragma unroll
        for (int rr = 0; rr < 2; rr++) {   // pw: 64x64 = 1024 float4
            int i = tid + rr * 512;
            int j = i >> 4, c4 = (i & 15) * 4;
            float4 w4 = *(const float4*)&proj_w[(size_t)(jc * 64 + j) * Cc + kc * 64 + c4];
            pw[j][c4] = w4.x; pw[j][c4 + 1] = w4.y; pw[j][c4 + 2] = w4.z; pw[j][c4 + 3] = w4.w;
        }
        __syncthreads();
#pragma unroll 8
        for (int c = 0; c < 64; c++) {
            float a = cs[ty][c];
            acc[0] = fmaf(a, pw[tx * 2 + 0][c], acc[0]);
            acc[1] = fmaf(a, pw[tx * 2 + 1][c], acc[1]);
        }
    }
    int j0 = jc * 64 + tx * 2;
    float2 pb = *(const float2*)&proj_b[j0];
    float2 v = make_float2(acc[0] + pb.x, acc[1] + pb.y);
    *(float2*)&out[(size_t)(r0 + ty) * Nt * Cc + j0] = v;
}

// ---------------- launch ----------------
extern "C" void kernel_launch(void* const* d_in, const int* in_sizes, int n_in,
                              void* d_out, int out_size) {
    (void)in_sizes; (void)n_in; (void)out_size;
    const float* x      = (const float*)d_in[0];
    const float* qkv_w  = (const float*)d_in[1];
    const float* qkv_b  = (const float*)d_in[2];
    const float* proj_w = (const float*)d_in[3];
    const float* proj_b = (const float*)d_in[4];
    float* out = (float*)d_out;

    k_qpart<<<dim3(12, 12), 512>>>(x, qkv_w);
    k_qsum <<<48, 256>>>(qkv_b);
    k_t    <<<dim3(12, 12), 512>>>(qkv_w, qkv_b);
    k_attn <<<dim3(64, SPLITS), 384>>>(x, out);
    k_ured <<<576, 256>>>();
    k_cls2 <<<dim3(12, 2), 512>>>(qkv_w, qkv_b);
    k_proj2<<<dim3(12, 4), 512>>>(proj_w, proj_b, out);
}

// round 14
// speedup vs baseline: 1.6163x; 1.6163x over previous
#include <cuda_runtime.h>
#include <cstdint>
#include <cstddef>

// Problem constants
#define Bb 64
#define Nt 577
#define Cc 768
#define Hh 12
#define SCv 0.125f
#define SPLITS 9
#define CHUNK 66        // 9*66 = 594 >= 577, divisible by G -> branchless groups
#define G 6             // tokens per group in k_attn
#define NG (CHUNK / G)  // 11 full groups per CTA

// ---------------- scratch (device globals; no allocation) ----------------
__device__ __align__(16) float g_qpart[12][Bb][Cc];            // q partial sums (kc,b,j)
__device__ __align__(16) float g_q[Bb][Cc];                    // q combined (+bias)
__device__ __align__(16) float g_t[Bb][Hh][Cc];                // SCALE * (q . Wk)
__device__ float            g_ob[Bb][Hh];                      // SCALE * (q . bk)
__device__ __align__(16) float g_pu[SPLITS][Bb][Hh][Cc];       // partial sum_n w*x
__device__ float            g_pd[SPLITS][Bb][Hh];              // partial sum_n w
__device__ __align__(16) float g_clsp[12][Bb][Cc];             // cls partials
__device__ __align__(16) float g_outp[12][Bb][Cc];             // proj partials

// ---------------- helpers ----------------
typedef unsigned long long ull;
__device__ __forceinline__ void fma2(ull &d, ull a, ull b) {
    asm("fma.rn.f32x2 %0, %1, %2, %0;" : "+l"(d) : "l"(a), "l"(b));
}
__device__ __forceinline__ float hadd2(ull a) {
    unsigned int lo, hi;
    asm("mov.b64 {%0,%1}, %2;" : "=r"(lo), "=r"(hi) : "l"(a));
    return __uint_as_float(lo) + __uint_as_float(hi);
}
__device__ __forceinline__ void cpa16(void* dst_smem, const void* src) {
    unsigned int d = (unsigned int)__cvta_generic_to_shared(dst_smem);
    asm volatile("cp.async.cg.shared.global [%0], [%1], 16;" :: "r"(d), "l"(src));
}

// ---------------- A1: q partials (k-split GEMM), 512 threads ----------------
__global__ void __launch_bounds__(512) k_qpart(const float* __restrict__ x,
                                               const float* __restrict__ qkv_w) {
    int jc = blockIdx.x, kc = blockIdx.y;
    __shared__ float xs[64][65];
    __shared__ float ws[64][65];
    int tid = threadIdx.x;
#pragma unroll
    for (int rr = 0; rr < 2; rr++) {
        int i = tid + rr * 512;
        int r = i >> 4, c4 = (i & 15) * 4;
        float4 xv = *(const float4*)&x[(size_t)r * Nt * Cc + kc * 64 + c4];
        xs[r][c4] = xv.x; xs[r][c4 + 1] = xv.y; xs[r][c4 + 2] = xv.z; xs[r][c4 + 3] = xv.w;
        float4 wv = *(const float4*)&qkv_w[(size_t)(jc * 64 + r) * Cc + kc * 64 + c4];
        ws[r][c4] = wv.x; ws[r][c4 + 1] = wv.y; ws[r][c4 + 2] = wv.z; ws[r][c4 + 3] = wv.w;
    }
    __syncthreads();
    int ty = tid >> 4, tx = tid & 15;     // 32 x 16
    float acc[2][4] = {};
#pragma unroll 8
    for (int d = 0; d < 64; d++) {
        float a0 = xs[ty * 2 + 0][d], a1 = xs[ty * 2 + 1][d];
        float b0 = ws[tx * 4 + 0][d], b1 = ws[tx * 4 + 1][d];
        float b2 = ws[tx * 4 + 2][d], b3 = ws[tx * 4 + 3][d];
        acc[0][0] += a0 * b0; acc[0][1] += a0 * b1; acc[0][2] += a0 * b2; acc[0][3] += a0 * b3;
        acc[1][0] += a1 * b0; acc[1][1] += a1 * b1; acc[1][2] += a1 * b2; acc[1][3] += a1 * b3;
    }
#pragma unroll
    for (int i = 0; i < 2; i++) {
        float4 v = make_float4(acc[i][0], acc[i][1], acc[i][2], acc[i][3]);
        *(float4*)&g_qpart[kc][ty * 2 + i][jc * 64 + tx * 4] = v;
    }
}

// ---------------- A1b: wide combine of q partials + bias (R3-proven) ----------------
__global__ void k_qsum(const float* __restrict__ qkv_b) {
    int idx = blockIdx.x * 256 + threadIdx.x;       // over Bb*Cc/4 = 12288
    if (idx >= Bb * Cc / 4) return;
    int b = idx / 192, j4 = (idx % 192) * 4;
    float4 s = *(const float4*)&qkv_b[j4];
#pragma unroll
    for (int kc = 0; kc < 12; kc++) {
        float4 p = *(const float4*)&g_qpart[kc][b][j4];
        s.x += p.x; s.y += p.y; s.z += p.z; s.w += p.w;
    }
    *(float4*)&g_q[b][j4] = s;
}

// ---------------- A2: t = SCALE*(q.Wk); ob, 512 thr (reads small g_q) ----------------
__global__ void __launch_bounds__(512) k_t(const float* __restrict__ qkv_w,
                                           const float* __restrict__ qkv_b) {
    int h = blockIdx.x, cc2 = blockIdx.y;
    __shared__ float qs[64][65];
    __shared__ float wk[64][65];
    int tid = threadIdx.x;
#pragma unroll
    for (int rr = 0; rr < 2; rr++) {
        int i = tid + rr * 512;
        int r = i >> 4, c4 = (i & 15) * 4;
        float4 qv = *(const float4*)&g_q[r][h * 64 + c4];
        qs[r][c4] = qv.x; qs[r][c4 + 1] = qv.y; qs[r][c4 + 2] = qv.z; qs[r][c4 + 3] = qv.w;
        float4 wv = *(const float4*)&qkv_w[(size_t)(Cc + h * 64 + r) * Cc + cc2 * 64 + c4];
        wk[r][c4] = wv.x; wk[r][c4 + 1] = wv.y; wk[r][c4 + 2] = wv.z; wk[r][c4 + 3] = wv.w;
    }
    __syncthreads();
    int ty = tid >> 4, tx = tid & 15;
    float acc[2][4] = {};
#pragma unroll 8
    for (int d = 0; d < 64; d++) {
        float a0 = qs[ty * 2 + 0][d], a1 = qs[ty * 2 + 1][d];
        float b0 = wk[d][tx * 4 + 0], b1 = wk[d][tx * 4 + 1];
        float b2 = wk[d][tx * 4 + 2], b3 = wk[d][tx * 4 + 3];
        acc[0][0] += a0 * b0; acc[0][1] += a0 * b1; acc[0][2] += a0 * b2; acc[0][3] += a0 * b3;
        acc[1][0] += a1 * b0; acc[1][1] += a1 * b1; acc[1][2] += a1 * b2; acc[1][3] += a1 * b3;
    }
#pragma unroll
    for (int i = 0; i < 2; i++) {
        float4 v = make_float4(SCv * acc[i][0], SCv * acc[i][1], SCv * acc[i][2], SCv * acc[i][3]);
        *(float4*)&g_t[ty * 2 + i][h][cc2 * 64 + tx * 4] = v;
    }
    if (cc2 == 0 && tid < 64) {
        float ssum = 0.f;
#pragma unroll 8
        for (int d = 0; d < 64; d++) ssum += qs[tid][d] * qkv_b[Cc + h * 64 + d];
        g_ob[tid][h] = SCv * ssum;
    }
}

// ---------------- B: main fused streaming kernel (R11, untouched) ----------------
__global__ void __launch_bounds__(384, 2) k_attn(const float* __restrict__ x,
                                                 float* __restrict__ out) {
    int b = blockIdx.x, sp = blockIdx.y;
    int n0 = sp * CHUNK;
    int tid = threadIdx.x;
    int w = tid >> 5, l = tid & 31;
    int g3 = l >> 3;
    int q = l & 7;

    __shared__ __align__(16) float xb[2][G][Cc];
    __shared__ __align__(16) float pl[G][12][12];
    __shared__ __align__(16) float wsm[G][16];
    __shared__ float obs[12];
    __shared__ float dsm[G * 12];

    int c1 = w * 64 + q * 8;
    ull t1[3][4];
#pragma unroll
    for (int i = 0; i < 3; i++) {
        ulonglong2 p0 = *(const ulonglong2*)&g_t[b][g3 * 3 + i][c1];
        ulonglong2 p1 = *(const ulonglong2*)&g_t[b][g3 * 3 + i][c1 + 4];
        t1[i][0] = p0.x; t1[i][1] = p0.y; t1[i][2] = p1.x; t1[i][3] = p1.y;
    }
    if (tid < 12) obs[tid] = g_ob[b][tid];

    int c2 = w * 64 + l * 2;
    float2 ua[12];
#pragma unroll
    for (int h = 0; h < 12; h++) ua[h] = make_float2(0.f, 0.f);
    float dp = 0.f;

    const float* xrow = x + (size_t)b * Nt * Cc;
    __syncthreads();

#pragma unroll
    for (int r = 0; r < 3; r++) {
        int i = tid + r * 384;
        int j = i / 192, off = (i % 192) * 4;
        int n = n0 + j; int nsrc = n < Nt ? n : Nt - 1;
        cpa16(&xb[0][j][off], xrow + (size_t)nsrc * Cc + off);
    }
    asm volatile("cp.async.commit_group;");

    for (int gi = 0; gi < NG; gi++) {
        int buf = gi & 1;
        int nbase = n0 + gi * G;
        if (gi + 1 < NG) {
            int nb2 = nbase + G;
#pragma unroll
            for (int r = 0; r < 3; r++) {
                int i = tid + r * 384;
                int j = i / 192, off = (i % 192) * 4;
                int n = nb2 + j; int nsrc = n < Nt ? n : Nt - 1;
                cpa16(&xb[buf ^ 1][j][off], xrow + (size_t)nsrc * Cc + off);
            }
        }
        asm volatile("cp.async.commit_group;");
        asm volatile("cp.async.wait_group 1;");
        __syncthreads();

        // ---- phase 1: logits ----
#pragma unroll
        for (int j = 0; j < G; j++) {
            ulonglong2 xp0 = *(const ulonglong2*)&xb[buf][j][c1];
            ulonglong2 xp1 = *(const ulonglong2*)&xb[buf][j][c1 + 4];
            ull xv0 = xp0.x, xv1 = xp0.y, xv2 = xp1.x, xv3 = xp1.y;
            float s[3];
#pragma unroll
            for (int i = 0; i < 3; i++) {
                ull a = 0ull;
                fma2(a, xv0, t1[i][0]); fma2(a, xv1, t1[i][1]);
                fma2(a, xv2, t1[i][2]); fma2(a, xv3, t1[i][3]);
                float sv = hadd2(a);
                sv += __shfl_xor_sync(0xffffffffu, sv, 4, 8);
                sv += __shfl_xor_sync(0xffffffffu, sv, 2, 8);
                sv += __shfl_xor_sync(0xffffffffu, sv, 1, 8);
                s[i] = sv;
            }
            if (q < 3) pl[j][w][g3 * 3 + q] = s[q];
        }
        __syncthreads();

        // ---- combine ----
        if (tid < G * 12) {
            int gg = tid / 12, h = tid % 12;
            int n = nbase + gg;
            float s = 0.f;
#pragma unroll
            for (int ww = 0; ww < 12; ww++) s += pl[gg][ww][h];
            float wv = (n < Nt) ? __expf(s + obs[h]) : 0.f;
            dp += wv;
            wsm[gg][h] = wv;
        }
        __syncthreads();

        // ---- phase 2 ----
#pragma unroll
        for (int j = 0; j < G; j++) {
            int n = nbase + j;
            float4 wA = *(const float4*)&wsm[j][0];
            float4 wB = *(const float4*)&wsm[j][4];
            float4 wC = *(const float4*)&wsm[j][8];
            float2 xv = *(const float2*)&xb[buf][j][c2];
            ua[0].x = fmaf(wA.x, xv.x, ua[0].x);  ua[0].y = fmaf(wA.x, xv.y, ua[0].y);
            ua[1].x = fmaf(wA.y, xv.x, ua[1].x);  ua[1].y = fmaf(wA.y, xv.y, ua[1].y);
            ua[2].x = fmaf(wA.z, xv.x, ua[2].x);  ua[2].y = fmaf(wA.z, xv.y, ua[2].y);
            ua[3].x = fmaf(wA.w, xv.x, ua[3].x);  ua[3].y = fmaf(wA.w, xv.y, ua[3].y);
            ua[4].x = fmaf(wB.x, xv.x, ua[4].x);  ua[4].y = fmaf(wB.x, xv.y, ua[4].y);
            ua[5].x = fmaf(wB.y, xv.x, ua[5].x);  ua[5].y = fmaf(wB.y, xv.y, ua[5].y);
            ua[6].x = fmaf(wB.z, xv.x, ua[6].x);  ua[6].y = fmaf(wB.z, xv.y, ua[6].y);
            ua[7].x = fmaf(wB.w, xv.x, ua[7].x);  ua[7].y = fmaf(wB.w, xv.y, ua[7].y);
            ua[8].x = fmaf(wC.x, xv.x, ua[8].x);  ua[8].y = fmaf(wC.x, xv.y, ua[8].y);
            ua[9].x = fmaf(wC.y, xv.x, ua[9].x);  ua[9].y = fmaf(wC.y, xv.y, ua[9].y);
            ua[10].x = fmaf(wC.z, xv.x, ua[10].x); ua[10].y = fmaf(wC.z, xv.y, ua[10].y);
            ua[11].x = fmaf(wC.w, xv.x, ua[11].x); ua[11].y = fmaf(wC.w, xv.y, ua[11].y);
            if (n > 0 && n < Nt)
                *(float2*)&out[((size_t)b * Nt + n) * Cc + c2] = xv;
        }
        __syncthreads();
    }

#pragma unroll
    for (int h = 0; h < 12; h++)
        *(float2*)&g_pu[sp][b][h][c2] = ua[h];
    if (tid < G * 12) dsm[tid] = dp;
    __syncthreads();
    if (tid < 12) {
        float s = 0.f;
#pragma unroll
        for (int gg = 0; gg < G; gg++) s += dsm[gg * 12 + tid];
        g_pd[sp][b][tid] = s;
    }
}

// ---------------- C1: cls partials (fused split-combine + normalize), 512 thr ----------------
__global__ void __launch_bounds__(512) k_cls(const float* __restrict__ qkv_w) {
    int h = blockIdx.x, kc = blockIdx.y;
    __shared__ float us[64][65];
    __shared__ float wv[64][65];
    __shared__ float dsh[64];
    int tid = threadIdx.x;
    if (tid < 64) {
        float s = 0.f;
#pragma unroll
        for (int sp = 0; sp < SPLITS; sp++) s += g_pd[sp][tid][h];
        dsh[tid] = 1.f / s;
    }
    __syncthreads();
#pragma unroll
    for (int rr = 0; rr < 2; rr++) {
        int i = tid + rr * 512;
        int r = i >> 4, c4 = (i & 15) * 4;
        float4 acc = make_float4(0.f, 0.f, 0.f, 0.f);
#pragma unroll
        for (int sp = 0; sp < SPLITS; sp++) {
            float4 p = *(const float4*)&g_pu[sp][r][h][kc * 64 + c4];
            acc.x += p.x; acc.y += p.y; acc.z += p.z; acc.w += p.w;
        }
        float inv = dsh[r];
        us[r][c4] = acc.x * inv; us[r][c4 + 1] = acc.y * inv;
        us[r][c4 + 2] = acc.z * inv; us[r][c4 + 3] = acc.w * inv;
        float4 wvv = *(const float4*)&qkv_w[(size_t)(2 * Cc + h * 64 + r) * Cc + kc * 64 + c4];
        wv[r][c4] = wvv.x; wv[r][c4 + 1] = wvv.y; wv[r][c4 + 2] = wvv.z; wv[r][c4 + 3] = wvv.w;
    }
    __syncthreads();
    int ty = tid >> 4, tx = tid & 15;
    float acc[2][4] = {};
#pragma unroll 8
    for (int c = 0; c < 64; c++) {
        float a0 = us[ty * 2 + 0][c], a1 = us[ty * 2 + 1][c];
        float b0 = wv[tx * 4 + 0][c], b1 = wv[tx * 4 + 1][c];
        float b2 = wv[tx * 4 + 2][c], b3 = wv[tx * 4 + 3][c];
        acc[0][0] += a0 * b0; acc[0][1] += a0 * b1; acc[0][2] += a0 * b2; acc[0][3] += a0 * b3;
        acc[1][0] += a1 * b0; acc[1][1] += a1 * b1; acc[1][2] += a1 * b2; acc[1][3] += a1 * b3;
    }
#pragma unroll
    for (int i = 0; i < 2; i++) {
        float4 v = make_float4(acc[i][0], acc[i][1], acc[i][2], acc[i][3]);
        *(float4*)&g_clsp[kc][ty * 2 + i][h * 64 + tx * 4] = v;
    }
}

// ---------------- C2: proj partials, 512 thr ----------------
__global__ void __launch_bounds__(512) k_proj(const float* __restrict__ qkv_b,
                                              const float* __restrict__ proj_w) {
    int jc = blockIdx.x, kc = blockIdx.y;
    __shared__ float cs[64][65];
    __shared__ float pw[64][65];
    int tid = threadIdx.x;
#pragma unroll
    for (int rr = 0; rr < 2; rr++) {
        int i = tid + rr * 512;
        int r = i >> 4, c4 = (i & 15) * 4;
        float4 s = *(const float4*)&qkv_b[2 * Cc + kc * 64 + c4];
#pragma unroll
        for (int p = 0; p < 12; p++) {
            float4 pv = *(const float4*)&g_clsp[p][r][kc * 64 + c4];
            s.x += pv.x; s.y += pv.y; s.z += pv.z; s.w += pv.w;
        }
        cs[r][c4] = s.x; cs[r][c4 + 1] = s.y; cs[r][c4 + 2] = s.z; cs[r][c4 + 3] = s.w;
        float4 wv = *(const float4*)&proj_w[(size_t)(jc * 64 + r) * Cc + kc * 64 + c4];
        pw[r][c4] = wv.x; pw[r][c4 + 1] = wv.y; pw[r][c4 + 2] = wv.z; pw[r][c4 + 3] = wv.w;
    }
    __syncthreads();
    int ty = tid >> 4, tx = tid & 15;
    float acc[2][4] = {};
#pragma unroll 8
    for (int c = 0; c < 64; c++) {
        float a0 = cs[ty * 2 + 0][c], a1 = cs[ty * 2 + 1][c];
        float b0 = pw[tx * 4 + 0][c], b1 = pw[tx * 4 + 1][c];
        float b2 = pw[tx * 4 + 2][c], b3 = pw[tx * 4 + 3][c];
        acc[0][0] += a0 * b0; acc[0][1] += a0 * b1; acc[0][2] += a0 * b2; acc[0][3] += a0 * b3;
        acc[1][0] += a1 * b0; acc[1][1] += a1 * b1; acc[1][2] += a1 * b2; acc[1][3] += a1 * b3;
    }
#pragma unroll
    for (int i = 0; i < 2; i++) {
        float4 v = make_float4(acc[i][0], acc[i][1], acc[i][2], acc[i][3]);
        *(float4*)&g_outp[kc][ty * 2 + i][jc * 64 + tx * 4] = v;
    }
}

// ---------------- C3: combine proj partials + proj_b -> out[:,0,:] ----------------
__global__ void k_final(const float* __restrict__ proj_b, float* __restrict__ out) {
    int idx = blockIdx.x * 256 + threadIdx.x;
    if (idx >= Bb * Cc / 4) return;
    int b = idx / 192, j4 = (idx % 192) * 4;
    float4 s = *(const float4*)&proj_b[j4];
#pragma unroll
    for (int p = 0; p < 12; p++) {
        float4 pv = *(const float4*)&g_outp[p][b][j4];
        s.x += pv.x; s.y += pv.y; s.z += pv.z; s.w += pv.w;
    }
    *(float4*)&out[(size_t)b * Nt * Cc + j4] = s;
}

// ---------------- launch ----------------
extern "C" void kernel_launch(void* const* d_in, const int* in_sizes, int n_in,
                              void* d_out, int out_size) {
    (void)in_sizes; (void)n_in; (void)out_size;
    const float* x      = (const float*)d_in[0];
    const float* qkv_w  = (const float*)d_in[1];
    const float* qkv_b  = (const float*)d_in[2];
    const float* proj_w = (const float*)d_in[3];
    const float* proj_b = (const float*)d_in[4];
    float* out = (float*)d_out;

    k_qpart<<<dim3(12, 12), 512>>>(x, qkv_w);
    k_qsum <<<48, 256>>>(qkv_b);
    k_t    <<<dim3(12, 12), 512>>>(qkv_w, qkv_b);
    k_attn <<<dim3(64, SPLITS), 384>>>(x, out);
    k_cls  <<<dim3(12, 12), 512>>>(qkv_w);
    k_proj <<<dim3(12, 12), 512>>>(qkv_b, proj_w);
    k_final<<<48, 256>>>(proj_b, out);
}